// round 12
// baseline (speedup 1.0000x reference)
#include <cuda_runtime.h>
#include <cuda_fp16.h>
#include <math.h>
#include <cstdint>

#define SQ 4096
#define FD 512

// ---- scratch (allocation-free: __device__ globals) ----
__device__ float g_qq[SQ * FD];      // fp32 qq (for qatt)
__device__ float g_qk[SQ * FD];      // fp32 q@Wk^T+bk (for qatt)
__device__ float g_qv[SQ * FD];      // fp32 q@Wv^T+bv (res epilogue)
__device__ float g_qatt[SQ];
__device__ float g_den[SQ];
__device__ __half g_qh[SQ * FD];     // fp16 inputs
__device__ __half g_kh[SQ * FD];
__device__ __half g_vh[SQ * FD];
__device__ __half g_Wqh[FD * FD];    // fp16 weights
__device__ __half g_Wkh[FD * FD];
__device__ __half g_Wvh[FD * FD];
__device__ __half g_Woh[FD * FD];
__device__ __half g_qqh[SQ * FD];    // fp16 relu'd projections
__device__ __half g_kkh[SQ * FD];
__device__ __half g_vvT[FD * SQ];    // vv transposed, K-major
__device__ __half g_resh[SQ * FD];   // fp16 res (A of out-proj)
__device__ __half g_scoresh[(size_t)SQ * SQ];  // fp16 raw scores (32MB)
__device__ __half g_ebf[(size_t)SQ * SQ];      // fp16 un-normalized exp (32MB)

// ================= helpers =================
__device__ __forceinline__ uint32_t smem_u32(const void* p) {
    uint32_t a;
    asm("{ .reg .u64 t; cvta.to.shared.u64 t, %1; cvt.u32.u64 %0, t; }" : "=r"(a) : "l"(p));
    return a;
}
__device__ __forceinline__ void ldsm4(uint32_t* r, uint32_t a) {
    asm volatile("ldmatrix.sync.aligned.m8n8.x4.shared.b16 {%0,%1,%2,%3}, [%4];"
                 : "=r"(r[0]), "=r"(r[1]), "=r"(r[2]), "=r"(r[3]) : "r"(a));
}
__device__ __forceinline__ void mma16816(float* c, const uint32_t* a, uint32_t b0, uint32_t b1) {
    asm volatile("mma.sync.aligned.m16n8k16.row.col.f32.f16.f16.f32 "
                 "{%0,%1,%2,%3}, {%4,%5,%6,%7}, {%8,%9}, {%0,%1,%2,%3};"
                 : "+f"(c[0]), "+f"(c[1]), "+f"(c[2]), "+f"(c[3])
                 : "r"(a[0]), "r"(a[1]), "r"(a[2]), "r"(a[3]), "r"(b0), "r"(b1));
}
__device__ __forceinline__ void cp16(uint32_t s, const void* g) {
    asm volatile("cp.async.cg.shared.global [%0], [%1], 16;" :: "r"(s), "l"(g));
}
#define CP_COMMIT() asm volatile("cp.async.commit_group;" ::: "memory")
#define CP_WAIT0()  asm volatile("cp.async.wait_group 0;" ::: "memory")
#define CP_WAIT1()  asm volatile("cp.async.wait_group 1;" ::: "memory")

// smem geometry: row = 32 halfs + 8 pad = 80B. BM fixed 128; BN = 32*G.
#define SAS 40
#define STAGE_A_BYTES (128 * 80)

// mainloop over one 32-K stage. 8 warps: 4m x 2n; warp tile 32 x 16G.
template <int G>
__device__ __forceinline__ void mainloop(uint32_t smA, uint32_t smB,
                                         int wm, int wn, int lane,
                                         float (&c)[2][2 * G][4]) {
    const int rowA = lane & 15, koffA = (lane >> 4) * 8;
    const int noffB = (lane & 7) + ((lane >> 4) << 3), koffB = ((lane >> 3) & 1) * 8;
#pragma unroll
    for (int ks = 0; ks < 2; ks++) {
        uint32_t a[2][4], b[G][4];
#pragma unroll
        for (int fm = 0; fm < 2; fm++)
            ldsm4(a[fm], smA + (uint32_t)(((wm * 32 + fm * 16 + rowA) * SAS + ks * 16 + koffA) * 2));
#pragma unroll
        for (int g = 0; g < G; g++)
            ldsm4(b[g], smB + (uint32_t)(((wn * 16 * G + g * 16 + noffB) * SAS + ks * 16 + koffB) * 2));
#pragma unroll
        for (int fm = 0; fm < 2; fm++)
#pragma unroll
            for (int g = 0; g < G; g++) {
                mma16816(c[fm][2 * g], a[fm], b[g][0], b[g][1]);
                mma16816(c[fm][2 * g + 1], a[fm], b[g][2], b[g][3]);
            }
    }
}

// ============================================================
// fp16 NT GEMM: C = A[M,K] @ B[N,K]^T, fp32 accum, 3-stage cp.async.
// BM=128, BN=32G, 256 thr. EPI 0: raw fp16 store. EPI 1: res epilogue.
// ============================================================
template <int G, int EPI>
__global__ void __launch_bounds__(256, 3)
h_gemm_nt(const __half* __restrict__ A, const __half* __restrict__ B,
          __half* __restrict__ O, int K, int ldc,
          const float* __restrict__ qv, const float* __restrict__ qatt,
          const float* __restrict__ den) {
    constexpr int BN = 32 * G;
    constexpr int STAGE_B = BN * 80;
    extern __shared__ char dsm[];
    const uint32_t baseA = smem_u32(dsm);
    const uint32_t baseB = baseA + 3 * STAGE_A_BYTES;

    const int tid = threadIdx.x, lane = tid & 31, wid = tid >> 5;
    const int wm = wid & 3, wn = wid >> 2;
    const int m0 = blockIdx.y * 128, n0 = blockIdx.x * BN;

    const int cr = tid >> 2;
    const int cc = (tid & 3) * 8;
    const int n = K >> 5;

    auto issue = [&](int chunk) {
        const int s = chunk % 3;
        const int k0 = chunk << 5;
        const uint32_t sa = baseA + s * STAGE_A_BYTES;
        const uint32_t sb = baseB + s * STAGE_B;
        cp16(sa + cr * 80 + cc * 2, A + (size_t)(m0 + cr) * K + k0 + cc);
        cp16(sa + (cr + 64) * 80 + cc * 2, A + (size_t)(m0 + cr + 64) * K + k0 + cc);
#pragma unroll
        for (int r = 0; r < BN; r += 64)
            cp16(sb + (cr + r) * 80 + cc * 2, B + (size_t)(n0 + cr + r) * K + k0 + cc);
        CP_COMMIT();
    };

    issue(0);
    issue(1);

    float c[2][2 * G][4] = {};

    for (int it = 0; it < n; it++) {
        if (it + 1 < n) { CP_WAIT1(); } else { CP_WAIT0(); }
        __syncthreads();
        if (it + 2 < n) issue(it + 2);
        mainloop<G>(baseA + (it % 3) * STAGE_A_BYTES, baseB + (it % 3) * STAGE_B,
                    wm, wn, lane, c);
    }

    // ---- epilogue ----
    const int rbase = m0 + wm * 32 + (lane >> 2);
    const int cbase = n0 + wn * 16 * G + (lane & 3) * 2;
#pragma unroll
    for (int fm = 0; fm < 2; fm++) {
        const int r = rbase + fm * 16;
        if (EPI == 0) {
#pragma unroll
            for (int j = 0; j < 2 * G; j++) {
                const int col = cbase + j * 8;
                *(__half2*)(O + (size_t)r * ldc + col) = __floats2half2_rn(c[fm][j][0], c[fm][j][1]);
                *(__half2*)(O + (size_t)(r + 8) * ldc + col) = __floats2half2_rn(c[fm][j][2], c[fm][j][3]);
            }
        } else {
            const float i0 = __frcp_rn(den[r]),     qa0 = qatt[r];
            const float i1 = __frcp_rn(den[r + 8]), qa1 = qatt[r + 8];
#pragma unroll
            for (int j = 0; j < 2 * G; j++) {
                const int col = cbase + j * 8;
                float2 v0 = *(const float2*)(qv + (size_t)r * ldc + col);
                float2 v1 = *(const float2*)(qv + (size_t)(r + 8) * ldc + col);
                *(__half2*)(O + (size_t)r * ldc + col) =
                    __floats2half2_rn(c[fm][j][0] * i0 + v0.x * qa0, c[fm][j][1] * i0 + v0.y * qa0);
                *(__half2*)(O + (size_t)(r + 8) * ldc + col) =
                    __floats2half2_rn(c[fm][j][2] * i1 + v1.x * qa1, c[fm][j][3] * i1 + v1.y * qa1);
            }
        }
    }
}

// ============================================================
// fp16 NT GEMM (projections), z-fused, BN=64 (G=2).
// ============================================================
struct ProjTab {
    const __half* A; const __half* B; const float* bias;
    float* Cf; __half* Ch; int hm; int relu;
};
struct ProjArgs { ProjTab t[5]; };

__global__ void __launch_bounds__(256, 3)
h_proj(ProjArgs pa) {
    constexpr int G = 2, BN = 64;
    constexpr int STAGE_B = BN * 80;
    const ProjTab T = pa.t[blockIdx.z];
    const __half* __restrict__ A = T.A;
    const __half* __restrict__ B = T.B;
    const int K = FD, N = FD;
    extern __shared__ char dsm[];
    const uint32_t baseA = smem_u32(dsm);
    const uint32_t baseB = baseA + 3 * STAGE_A_BYTES;

    const int tid = threadIdx.x, lane = tid & 31, wid = tid >> 5;
    const int wm = wid & 3, wn = wid >> 2;
    const int m0 = blockIdx.y * 128, n0 = blockIdx.x * BN;

    const int cr = tid >> 2;
    const int cc = (tid & 3) * 8;
    const int n = K >> 5;  // 16

    auto issue = [&](int chunk) {
        const int s = chunk % 3;
        const int k0 = chunk << 5;
        const uint32_t sa = baseA + s * STAGE_A_BYTES;
        const uint32_t sb = baseB + s * STAGE_B;
        cp16(sa + cr * 80 + cc * 2, A + (size_t)(m0 + cr) * K + k0 + cc);
        cp16(sa + (cr + 64) * 80 + cc * 2, A + (size_t)(m0 + cr + 64) * K + k0 + cc);
        cp16(sb + cr * 80 + cc * 2, B + (size_t)(n0 + cr) * K + k0 + cc);
        CP_COMMIT();
    };

    issue(0);
    issue(1);

    float c[2][2 * G][4] = {};

    for (int it = 0; it < n; it++) {
        if (it + 1 < n) { CP_WAIT1(); } else { CP_WAIT0(); }
        __syncthreads();
        if (it + 2 < n) issue(it + 2);
        mainloop<G>(baseA + (it % 3) * STAGE_A_BYTES, baseB + (it % 3) * STAGE_B,
                    wm, wn, lane, c);
    }

    // ---- epilogue ----
    const int rbase = m0 + wm * 32 + (lane >> 2);
    const int cbase = n0 + wn * 16 * G + (lane & 3) * 2;
    float* Cf = T.Cf;
    __half* Ch = T.Ch;
    const int hm = T.hm, relu = T.relu;
#pragma unroll
    for (int fm = 0; fm < 2; fm++) {
#pragma unroll
        for (int j = 0; j < 2 * G; j++) {
            const int col = cbase + j * 8;
            const float b0 = T.bias[col], b1 = T.bias[col + 1];
#pragma unroll
            for (int h = 0; h < 2; h++) {
                const int r = rbase + fm * 16 + h * 8;
                float v0 = c[fm][j][2 * h] + b0;
                float v1 = c[fm][j][2 * h + 1] + b1;
                if (relu) { v0 = fmaxf(v0, 0.0f); v1 = fmaxf(v1, 0.0f); }
                if (Cf) *(float2*)(Cf + (size_t)r * N + col) = make_float2(v0, v1);
                if (hm == 1) {
                    *(__half2*)(Ch + (size_t)r * N + col) = __floats2half2_rn(v0, v1);
                } else if (hm == 2) {
                    Ch[(size_t)col * SQ + r] = __float2half_rn(v0);
                    Ch[(size_t)(col + 1) * SQ + r] = __float2half_rn(v1);
                }
            }
        }
    }
}

// ============================================================
// fp32 -> fp16 conversion, z-segmented
// ============================================================
struct CvtTab { const float* src; __half* dst; int n; };
struct CvtArgs { CvtTab t[7]; };

__global__ void f2h_kernel(CvtArgs a) {
    const CvtTab T = a.t[blockIdx.z];
    const int i = (blockIdx.x * blockDim.x + threadIdx.x) * 4;
    if (i < T.n) {
        float4 v = *(const float4*)(T.src + i);
        __half2 h0 = __floats2half2_rn(v.x, v.y);
        __half2 h1 = __floats2half2_rn(v.z, v.w);
        *(uint2*)(T.dst + i) = make_uint2(*(uint32_t*)&h0, *(uint32_t*)&h1);
    }
}

// ============================================================
// q_att[s] = sum_f qq[s,f]*qk[s,f]   (fp32)
// ============================================================
__global__ void qatt_kernel(const float* __restrict__ qq, const float* __restrict__ qk,
                            float* __restrict__ qatt) {
    const int warp = (blockIdx.x * blockDim.x + threadIdx.x) >> 5;
    const int lane = threadIdx.x & 31;
    if (warp >= SQ) return;
    const float4* a = (const float4*)(qq + (size_t)warp * FD);
    const float4* b = (const float4*)(qk + (size_t)warp * FD);
    float sum = 0.0f;
#pragma unroll
    for (int i = lane; i < FD / 4; i += 32) {
        float4 x = a[i], y = b[i];
        sum = fmaf(x.x, y.x, sum); sum = fmaf(x.y, y.y, sum);
        sum = fmaf(x.z, y.z, sum); sum = fmaf(x.w, y.w, sum);
    }
#pragma unroll
    for (int o = 16; o; o >>= 1) sum += __shfl_xor_sync(0xffffffffu, sum, o);
    if (lane == 0) qatt[warp] = sum;
}

// ============================================================
// Row softmax w/ sink: fp16 scores -> fp16 un-normalized exp + fp32 denom
// ============================================================
__global__ void softmax_kernel(const __half* __restrict__ scores, __half* __restrict__ ebf,
                               const float* __restrict__ qatt, float* __restrict__ den) {
    const int s = blockIdx.x;
    const int tid = threadIdx.x;  // 256
    const float inv = rsqrtf(513.0f);
    const uint4* row8 = (const uint4*)(scores + (size_t)s * SQ);
    uint4* erow8 = (uint4*)(ebf + (size_t)s * SQ);
    const float sink = qatt[s] * inv;

    __shared__ float sm_max[8];
    __shared__ float sm_sum[8];

    float m = sink;
#pragma unroll
    for (int i = tid; i < SQ / 8; i += 256) {
        uint4 u = row8[i];
        const __half2* h = (const __half2*)&u;
#pragma unroll
        for (int p = 0; p < 4; p++) {
            float2 f = __half22float2(h[p]);
            m = fmaxf(m, fmaxf(f.x, f.y) * inv);
        }
    }
#pragma unroll
    for (int o = 16; o; o >>= 1) m = fmaxf(m, __shfl_xor_sync(0xffffffffu, m, o));
    if ((tid & 31) == 0) sm_max[tid >> 5] = m;
    __syncthreads();
    m = sm_max[0];
#pragma unroll
    for (int i = 1; i < 8; i++) m = fmaxf(m, sm_max[i]);

    float lsum = (tid == 0) ? __expf(sink - m) : 0.0f;
#pragma unroll
    for (int i = tid; i < SQ / 8; i += 256) {
        uint4 u = row8[i];
        const __half2* h = (const __half2*)&u;
        uint4 o;
        __half2* oh = (__half2*)&o;
#pragma unroll
        for (int p = 0; p < 4; p++) {
            float2 f = __half22float2(h[p]);
            float e0 = __expf(f.x * inv - m);
            float e1 = __expf(f.y * inv - m);
            oh[p] = __floats2half2_rn(e0, e1);
            lsum += e0 + e1;
        }
        erow8[i] = o;
    }
#pragma unroll
    for (int o = 16; o; o >>= 1) lsum += __shfl_xor_sync(0xffffffffu, lsum, o);
    if ((tid & 31) == 0) sm_sum[tid >> 5] = lsum;
    __syncthreads();
    if (tid == 0) {
        float t = 0.0f;
#pragma unroll
        for (int i = 0; i < 8; i++) t += sm_sum[i];
        den[s] = t;
    }
}

// ============================================================
extern "C" void kernel_launch(void* const* d_in, const int* in_sizes, int n_in,
                              void* d_out, int out_size) {
    const float* q  = (const float*)d_in[0];
    const float* k  = (const float*)d_in[1];
    const float* v  = (const float*)d_in[2];
    const float* Wq = (const float*)d_in[3];
    const float* bq = (const float*)d_in[4];
    const float* Wk = (const float*)d_in[5];
    const float* bk = (const float*)d_in[6];
    const float* Wv = (const float*)d_in[7];
    const float* bv = (const float*)d_in[8];
    const float* Wo = (const float*)d_in[9];
    const float* bo = (const float*)d_in[10];
    float* out = (float*)d_out;

    float *qq, *qk, *qv, *qatt, *den;
    __half *qh, *kh, *vh, *Wqh, *Wkh, *Wvh, *Woh;
    __half *qqh, *kkh, *vvT, *resh, *scoresh, *ebf;
    cudaGetSymbolAddress((void**)&qq, g_qq);
    cudaGetSymbolAddress((void**)&qk, g_qk);
    cudaGetSymbolAddress((void**)&qv, g_qv);
    cudaGetSymbolAddress((void**)&qatt, g_qatt);
    cudaGetSymbolAddress((void**)&den, g_den);
    cudaGetSymbolAddress((void**)&qh, g_qh);
    cudaGetSymbolAddress((void**)&kh, g_kh);
    cudaGetSymbolAddress((void**)&vh, g_vh);
    cudaGetSymbolAddress((void**)&Wqh, g_Wqh);
    cudaGetSymbolAddress((void**)&Wkh, g_Wkh);
    cudaGetSymbolAddress((void**)&Wvh, g_Wvh);
    cudaGetSymbolAddress((void**)&Woh, g_Woh);
    cudaGetSymbolAddress((void**)&qqh, g_qqh);
    cudaGetSymbolAddress((void**)&kkh, g_kkh);
    cudaGetSymbolAddress((void**)&vvT, g_vvT);
    cudaGetSymbolAddress((void**)&resh, g_resh);
    cudaGetSymbolAddress((void**)&scoresh, g_scoresh);
    cudaGetSymbolAddress((void**)&ebf, g_ebf);

    const int gSmem = 3 * STAGE_A_BYTES + 3 * 64 * 80;  // 46080 (BN=64)
    cudaFuncSetAttribute((const void*)h_gemm_nt<2, 0>, cudaFuncAttributeMaxDynamicSharedMemorySize, gSmem);
    cudaFuncSetAttribute((const void*)h_gemm_nt<2, 1>, cudaFuncAttributeMaxDynamicSharedMemorySize, gSmem);
    cudaFuncSetAttribute((const void*)h_proj, cudaFuncAttributeMaxDynamicSharedMemorySize, gSmem);

    // 1) fp32 -> fp16 conversions (inputs + weights)
    CvtArgs ca;
    ca.t[0] = { q, qh, SQ * FD };
    ca.t[1] = { k, kh, SQ * FD };
    ca.t[2] = { v, vh, SQ * FD };
    ca.t[3] = { Wq, Wqh, FD * FD };
    ca.t[4] = { Wk, Wkh, FD * FD };
    ca.t[5] = { Wv, Wvh, FD * FD };
    ca.t[6] = { Wo, Woh, FD * FD };
    f2h_kernel<<<dim3(SQ * FD / 1024, 1, 7), 256>>>(ca);

    // 2) 5 fused projections (fp16 HMMA, BN=64)
    ProjArgs pa;
    pa.t[0] = { qh, Wqh, bq, qq,      qqh,     1, 1 };
    pa.t[1] = { kh, Wkh, bk, nullptr, kkh,     1, 1 };
    pa.t[2] = { vh, Wvh, bv, nullptr, vvT,     2, 1 };
    pa.t[3] = { qh, Wkh, bk, qk,      nullptr, 0, 0 };
    pa.t[4] = { qh, Wvh, bv, qv,      nullptr, 0, 0 };
    h_proj<<<dim3(FD / 64, SQ / 128, 5), 256, gSmem>>>(pa);

    // 3) q_att diag term (fp32)
    qatt_kernel<<<SQ / 8, 256>>>(qq, qk, qatt);

    // 4) scores = qq @ kk^T  (fp16 HMMA, BN=64, fp16 store)
    h_gemm_nt<2, 0><<<dim3(SQ / 64, SQ / 128), 256, gSmem>>>(
        qqh, kkh, scoresh, FD, SQ, nullptr, nullptr, nullptr);

    // 5) softmax w/ sink
    softmax_kernel<<<SQ, 256>>>(scoresh, ebf, qatt, den);

    // 6) res = (E @ vv)/den + qv*qatt  -> fp16 resh (BN=64)
    h_gemm_nt<2, 1><<<dim3(FD / 64, SQ / 128), 256, gSmem>>>(
        ebf, vvT, resh, SQ, FD, qv, qatt, den);

    // 7) y = relu(res @ Wo^T + bo)  (fp16 HMMA, fp32 out)
    ProjArgs po;
    po.t[0] = { resh, Woh, bo, out, nullptr, 0, 1 };
    po.t[1] = po.t[0]; po.t[2] = po.t[0]; po.t[3] = po.t[0]; po.t[4] = po.t[0];
    h_proj<<<dim3(FD / 64, SQ / 128, 1), 256, gSmem>>>(po);
}

// round 13
// speedup vs baseline: 1.0397x; 1.0397x over previous
#include <cuda_runtime.h>
#include <cuda_fp16.h>
#include <math.h>
#include <cstdint>

#define SQ 4096
#define FD 512

// ---- scratch (allocation-free: __device__ globals) ----
__device__ float g_qq[SQ * FD];      // fp32 qq (for qatt)
__device__ float g_qk[SQ * FD];      // fp32 q@Wk^T+bk (for qatt)
__device__ float g_qv[SQ * FD];      // fp32 q@Wv^T+bv (res epilogue)
__device__ float g_qatt[SQ];
__device__ float g_den[SQ];
__device__ __half g_qh[SQ * FD];     // fp16 inputs
__device__ __half g_kh[SQ * FD];
__device__ __half g_vh[SQ * FD];
__device__ __half g_Wqh[FD * FD];    // fp16 weights
__device__ __half g_Wkh[FD * FD];
__device__ __half g_Wvh[FD * FD];
__device__ __half g_Woh[FD * FD];
__device__ __half g_qqh[SQ * FD];    // fp16 relu'd projections
__device__ __half g_kkh[SQ * FD];
__device__ __half g_vvT[FD * SQ];    // vv transposed, K-major
__device__ __half g_resh[SQ * FD];   // fp16 res (A of out-proj)
__device__ __half g_ebf[(size_t)SQ * SQ];  // fp16 un-normalized exp (32MB)

#define INV_SCALE 0.04419417382415922f   // 1/sqrt(513)
#define EXP_SHIFT 4.1588830833596715f    // 6*ln2 : keeps fp16 exp in range

// ================= helpers =================
__device__ __forceinline__ uint32_t smem_u32(const void* p) {
    uint32_t a;
    asm("{ .reg .u64 t; cvta.to.shared.u64 t, %1; cvt.u32.u64 %0, t; }" : "=r"(a) : "l"(p));
    return a;
}
__device__ __forceinline__ void ldsm4(uint32_t* r, uint32_t a) {
    asm volatile("ldmatrix.sync.aligned.m8n8.x4.shared.b16 {%0,%1,%2,%3}, [%4];"
                 : "=r"(r[0]), "=r"(r[1]), "=r"(r[2]), "=r"(r[3]) : "r"(a));
}
__device__ __forceinline__ void mma16816(float* c, const uint32_t* a, uint32_t b0, uint32_t b1) {
    asm volatile("mma.sync.aligned.m16n8k16.row.col.f32.f16.f16.f32 "
                 "{%0,%1,%2,%3}, {%4,%5,%6,%7}, {%8,%9}, {%0,%1,%2,%3};"
                 : "+f"(c[0]), "+f"(c[1]), "+f"(c[2]), "+f"(c[3])
                 : "r"(a[0]), "r"(a[1]), "r"(a[2]), "r"(a[3]), "r"(b0), "r"(b1));
}
__device__ __forceinline__ void cp16(uint32_t s, const void* g) {
    asm volatile("cp.async.cg.shared.global [%0], [%1], 16;" :: "r"(s), "l"(g));
}
#define CP_COMMIT() asm volatile("cp.async.commit_group;" ::: "memory")
#define CP_WAIT0()  asm volatile("cp.async.wait_group 0;" ::: "memory")
#define CP_WAIT1()  asm volatile("cp.async.wait_group 1;" ::: "memory")

// smem geometry shared by all fp16 GEMMs: row = 32 halfs + 8 pad = 80B
#define SAS 40
#define STAGE_BYTES (128 * SAS * 2)   // 10240 per operand stage

// mainloop fragment offsets
#define FRAG_SETUP() \
    const int rowA = lane & 15, koffA = (lane >> 4) * 8; \
    const int noffB = (lane & 7) + ((lane >> 4) << 3), koffB = ((lane >> 3) & 1) * 8;

#define MAINLOOP_BODY(smA, smB) \
    _Pragma("unroll") \
    for (int ks = 0; ks < 2; ks++) { \
        uint32_t a[2][4], b[4][4]; \
        _Pragma("unroll") \
        for (int fm = 0; fm < 2; fm++) \
            ldsm4(a[fm], (smA) + (uint32_t)(((wm * 32 + fm * 16 + rowA) * SAS + ks * 16 + koffA) * 2)); \
        _Pragma("unroll") \
        for (int g = 0; g < 4; g++) \
            ldsm4(b[g], (smB) + (uint32_t)(((wn * 64 + g * 16 + noffB) * SAS + ks * 16 + koffB) * 2)); \
        _Pragma("unroll") \
        for (int fm = 0; fm < 2; fm++) \
            _Pragma("unroll") \
            for (int g = 0; g < 4; g++) { \
                mma16816(c[fm][2 * g], a[fm], b[g][0], b[g][1]); \
                mma16816(c[fm][2 * g + 1], a[fm], b[g][2], b[g][3]); \
            } \
    }

// ============================================================
// fp16 NT GEMM (attention): C = A[M,K] @ B[N,K]^T, fp32 accum.
// BM=BN=128, BK=32, 256 thr (8 warps 4m x 2n), 3-stage cp.async.
// EPI 0: scores->exp fusion: store fp16 exp(acc*inv - C), atomicAdd row
//        partial sums into den[].
// EPI 1: resh = acc/den[r] + qv*qatt (fp16 store).
// ============================================================
template <int EPI>
__global__ void __launch_bounds__(256)
h_gemm_nt(const __half* __restrict__ A, const __half* __restrict__ B,
          __half* __restrict__ O, int K, int ldc,
          const float* __restrict__ qv, const float* __restrict__ qatt,
          float* __restrict__ den) {
    extern __shared__ char dsm[];
    const uint32_t baseA = smem_u32(dsm);
    const uint32_t baseB = baseA + 3 * STAGE_BYTES;

    const int tid = threadIdx.x, lane = tid & 31, wid = tid >> 5;
    const int wm = wid & 3, wn = wid >> 2;
    const int m0 = blockIdx.y * 128, n0 = blockIdx.x * 128;

    const int cr = tid >> 2;
    const int cc = (tid & 3) * 8;
    const int n = K >> 5;

    auto issue = [&](int chunk) {
        const int s = chunk % 3;
        const int k0 = chunk << 5;
        const uint32_t sa = baseA + s * STAGE_BYTES;
        const uint32_t sb = baseB + s * STAGE_BYTES;
        cp16(sa + cr * 80 + cc * 2, A + (size_t)(m0 + cr) * K + k0 + cc);
        cp16(sa + (cr + 64) * 80 + cc * 2, A + (size_t)(m0 + cr + 64) * K + k0 + cc);
        cp16(sb + cr * 80 + cc * 2, B + (size_t)(n0 + cr) * K + k0 + cc);
        cp16(sb + (cr + 64) * 80 + cc * 2, B + (size_t)(n0 + cr + 64) * K + k0 + cc);
        CP_COMMIT();
    };

    issue(0);
    issue(1);

    FRAG_SETUP();
    float c[2][8][4] = {};

    for (int it = 0; it < n; it++) {
        if (it + 1 < n) { CP_WAIT1(); } else { CP_WAIT0(); }
        __syncthreads();
        if (it + 2 < n) issue(it + 2);
        const uint32_t smA = baseA + (it % 3) * STAGE_BYTES;
        const uint32_t smB = baseB + (it % 3) * STAGE_BYTES;
        MAINLOOP_BODY(smA, smB);
    }

    // ---- epilogue ----
    const int rbase = m0 + wm * 32 + (lane >> 2);
    const int cbase = n0 + wn * 64 + (lane & 3) * 2;
#pragma unroll
    for (int fm = 0; fm < 2; fm++) {
        const int r = rbase + fm * 16;
        if (EPI == 0) {
            // exp + row-sum fusion (softmax kernel eliminated)
            float p0 = 0.0f, p1 = 0.0f;
#pragma unroll
            for (int j = 0; j < 8; j++) {
                const int col = cbase + j * 8;
                float e0 = __expf(c[fm][j][0] * INV_SCALE - EXP_SHIFT);
                float e1 = __expf(c[fm][j][1] * INV_SCALE - EXP_SHIFT);
                float e2 = __expf(c[fm][j][2] * INV_SCALE - EXP_SHIFT);
                float e3 = __expf(c[fm][j][3] * INV_SCALE - EXP_SHIFT);
                *(__half2*)(O + (size_t)r * ldc + col) = __floats2half2_rn(e0, e1);
                *(__half2*)(O + (size_t)(r + 8) * ldc + col) = __floats2half2_rn(e2, e3);
                p0 += e0 + e1;
                p1 += e2 + e3;
            }
            // reduce across the 4 lanes sharing each row (lane bits 0-1)
            p0 += __shfl_xor_sync(0xffffffffu, p0, 1);
            p0 += __shfl_xor_sync(0xffffffffu, p0, 2);
            p1 += __shfl_xor_sync(0xffffffffu, p1, 1);
            p1 += __shfl_xor_sync(0xffffffffu, p1, 2);
            if ((lane & 3) == 0) {
                atomicAdd(den + r, p0);
                atomicAdd(den + r + 8, p1);
            }
        } else {
            const float i0 = __frcp_rn(den[r]),     qa0 = qatt[r];
            const float i1 = __frcp_rn(den[r + 8]), qa1 = qatt[r + 8];
#pragma unroll
            for (int j = 0; j < 8; j++) {
                const int col = cbase + j * 8;
                float2 v0 = *(const float2*)(qv + (size_t)r * ldc + col);
                float2 v1 = *(const float2*)(qv + (size_t)(r + 8) * ldc + col);
                *(__half2*)(O + (size_t)r * ldc + col) =
                    __floats2half2_rn(c[fm][j][0] * i0 + v0.x * qa0, c[fm][j][1] * i0 + v0.y * qa0);
                *(__half2*)(O + (size_t)(r + 8) * ldc + col) =
                    __floats2half2_rn(c[fm][j][2] * i1 + v1.x * qa1, c[fm][j][3] * i1 + v1.y * qa1);
            }
        }
    }
}

// ============================================================
// fp16 NT GEMM (projections), z-fused table:
//   per-z: Cf?=fp32 out, Ch?=fp16 out (hm 1=row, 2=transposed), bias, relu.
// Same tile/pipeline as h_gemm_nt. K = N = FD.
// ============================================================
struct ProjTab {
    const __half* A; const __half* B; const float* bias;
    float* Cf; __half* Ch; int hm; int relu;
};
struct ProjArgs { ProjTab t[5]; };

__global__ void __launch_bounds__(256)
h_proj(ProjArgs pa) {
    const ProjTab T = pa.t[blockIdx.z];
    const __half* __restrict__ A = T.A;
    const __half* __restrict__ B = T.B;
    const int K = FD, N = FD;
    extern __shared__ char dsm[];
    const uint32_t baseA = smem_u32(dsm);
    const uint32_t baseB = baseA + 3 * STAGE_BYTES;

    const int tid = threadIdx.x, lane = tid & 31, wid = tid >> 5;
    const int wm = wid & 3, wn = wid >> 2;
    const int m0 = blockIdx.y * 128, n0 = blockIdx.x * 128;

    const int cr = tid >> 2;
    const int cc = (tid & 3) * 8;
    const int n = K >> 5;  // 16

    auto issue = [&](int chunk) {
        const int s = chunk % 3;
        const int k0 = chunk << 5;
        const uint32_t sa = baseA + s * STAGE_BYTES;
        const uint32_t sb = baseB + s * STAGE_BYTES;
        cp16(sa + cr * 80 + cc * 2, A + (size_t)(m0 + cr) * K + k0 + cc);
        cp16(sa + (cr + 64) * 80 + cc * 2, A + (size_t)(m0 + cr + 64) * K + k0 + cc);
        cp16(sb + cr * 80 + cc * 2, B + (size_t)(n0 + cr) * K + k0 + cc);
        cp16(sb + (cr + 64) * 80 + cc * 2, B + (size_t)(n0 + cr + 64) * K + k0 + cc);
        CP_COMMIT();
    };

    issue(0);
    issue(1);

    FRAG_SETUP();
    float c[2][8][4] = {};

    for (int it = 0; it < n; it++) {
        if (it + 1 < n) { CP_WAIT1(); } else { CP_WAIT0(); }
        __syncthreads();
        if (it + 2 < n) issue(it + 2);
        const uint32_t smA = baseA + (it % 3) * STAGE_BYTES;
        const uint32_t smB = baseB + (it % 3) * STAGE_BYTES;
        MAINLOOP_BODY(smA, smB);
    }

    // ---- epilogue ----
    const int rbase = m0 + wm * 32 + (lane >> 2);
    const int cbase = n0 + wn * 64 + (lane & 3) * 2;
    float* Cf = T.Cf;
    __half* Ch = T.Ch;
    const int hm = T.hm, relu = T.relu;
#pragma unroll
    for (int fm = 0; fm < 2; fm++) {
#pragma unroll
        for (int j = 0; j < 8; j++) {
            const int col = cbase + j * 8;
            const float b0 = T.bias[col], b1 = T.bias[col + 1];
#pragma unroll
            for (int h = 0; h < 2; h++) {
                const int r = rbase + fm * 16 + h * 8;
                float v0 = c[fm][j][2 * h] + b0;
                float v1 = c[fm][j][2 * h + 1] + b1;
                if (relu) { v0 = fmaxf(v0, 0.0f); v1 = fmaxf(v1, 0.0f); }
                if (Cf) *(float2*)(Cf + (size_t)r * N + col) = make_float2(v0, v1);
                if (hm == 1) {
                    *(__half2*)(Ch + (size_t)r * N + col) = __floats2half2_rn(v0, v1);
                } else if (hm == 2) {
                    Ch[(size_t)col * SQ + r] = __float2half_rn(v0);
                    Ch[(size_t)(col + 1) * SQ + r] = __float2half_rn(v1);
                }
            }
        }
    }
}

// ============================================================
// fp32 -> fp16 conversion, z-segmented
// ============================================================
struct CvtTab { const float* src; __half* dst; int n; };
struct CvtArgs { CvtTab t[7]; };

__global__ void f2h_kernel(CvtArgs a) {
    const CvtTab T = a.t[blockIdx.z];
    const int i = (blockIdx.x * blockDim.x + threadIdx.x) * 4;
    if (i < T.n) {
        float4 v = *(const float4*)(T.src + i);
        __half2 h0 = __floats2half2_rn(v.x, v.y);
        __half2 h1 = __floats2half2_rn(v.z, v.w);
        *(uint2*)(T.dst + i) = make_uint2(*(uint32_t*)&h0, *(uint32_t*)&h1);
    }
}

// ============================================================
// q_att[s] = sum_f qq[s,f]*qk[s,f]   (fp32)
// Also initializes den[s] with the softmax sink term exp(qatt*inv - C).
// ============================================================
__global__ void qatt_kernel(const float* __restrict__ qq, const float* __restrict__ qk,
                            float* __restrict__ qatt, float* __restrict__ den) {
    const int warp = (blockIdx.x * blockDim.x + threadIdx.x) >> 5;
    const int lane = threadIdx.x & 31;
    if (warp >= SQ) return;
    const float4* a = (const float4*)(qq + (size_t)warp * FD);
    const float4* b = (const float4*)(qk + (size_t)warp * FD);
    float sum = 0.0f;
#pragma unroll
    for (int i = lane; i < FD / 4; i += 32) {
        float4 x = a[i], y = b[i];
        sum = fmaf(x.x, y.x, sum); sum = fmaf(x.y, y.y, sum);
        sum = fmaf(x.z, y.z, sum); sum = fmaf(x.w, y.w, sum);
    }
#pragma unroll
    for (int o = 16; o; o >>= 1) sum += __shfl_xor_sync(0xffffffffu, sum, o);
    if (lane == 0) {
        qatt[warp] = sum;
        den[warp] = __expf(sum * INV_SCALE - EXP_SHIFT);  // sink term, re-inits den
    }
}

// ============================================================
extern "C" void kernel_launch(void* const* d_in, const int* in_sizes, int n_in,
                              void* d_out, int out_size) {
    const float* q  = (const float*)d_in[0];
    const float* k  = (const float*)d_in[1];
    const float* v  = (const float*)d_in[2];
    const float* Wq = (const float*)d_in[3];
    const float* bq = (const float*)d_in[4];
    const float* Wk = (const float*)d_in[5];
    const float* bk = (const float*)d_in[6];
    const float* Wv = (const float*)d_in[7];
    const float* bv = (const float*)d_in[8];
    const float* Wo = (const float*)d_in[9];
    const float* bo = (const float*)d_in[10];
    float* out = (float*)d_out;

    float *qq, *qk, *qv, *qatt, *den;
    __half *qh, *kh, *vh, *Wqh, *Wkh, *Wvh, *Woh;
    __half *qqh, *kkh, *vvT, *resh, *ebf;
    cudaGetSymbolAddress((void**)&qq, g_qq);
    cudaGetSymbolAddress((void**)&qk, g_qk);
    cudaGetSymbolAddress((void**)&qv, g_qv);
    cudaGetSymbolAddress((void**)&qatt, g_qatt);
    cudaGetSymbolAddress((void**)&den, g_den);
    cudaGetSymbolAddress((void**)&qh, g_qh);
    cudaGetSymbolAddress((void**)&kh, g_kh);
    cudaGetSymbolAddress((void**)&vh, g_vh);
    cudaGetSymbolAddress((void**)&Wqh, g_Wqh);
    cudaGetSymbolAddress((void**)&Wkh, g_Wkh);
    cudaGetSymbolAddress((void**)&Wvh, g_Wvh);
    cudaGetSymbolAddress((void**)&Woh, g_Woh);
    cudaGetSymbolAddress((void**)&qqh, g_qqh);
    cudaGetSymbolAddress((void**)&kkh, g_kkh);
    cudaGetSymbolAddress((void**)&vvT, g_vvT);
    cudaGetSymbolAddress((void**)&resh, g_resh);
    cudaGetSymbolAddress((void**)&ebf, g_ebf);

    const int gSmem = 6 * STAGE_BYTES;  // 61440
    cudaFuncSetAttribute(h_gemm_nt<0>, cudaFuncAttributeMaxDynamicSharedMemorySize, gSmem);
    cudaFuncSetAttribute(h_gemm_nt<1>, cudaFuncAttributeMaxDynamicSharedMemorySize, gSmem);
    cudaFuncSetAttribute(h_proj, cudaFuncAttributeMaxDynamicSharedMemorySize, gSmem);

    // 1) fp32 -> fp16 conversions (inputs + weights)
    CvtArgs ca;
    ca.t[0] = { q, qh, SQ * FD };
    ca.t[1] = { k, kh, SQ * FD };
    ca.t[2] = { v, vh, SQ * FD };
    ca.t[3] = { Wq, Wqh, FD * FD };
    ca.t[4] = { Wk, Wkh, FD * FD };
    ca.t[5] = { Wv, Wvh, FD * FD };
    ca.t[6] = { Wo, Woh, FD * FD };
    f2h_kernel<<<dim3(SQ * FD / 1024, 1, 7), 256>>>(ca);

    // 2) 5 fused projections (fp16 HMMA)
    ProjArgs pa;
    pa.t[0] = { qh, Wqh, bq, qq,      qqh,     1, 1 };  // qq fp32 + fp16 row
    pa.t[1] = { kh, Wkh, bk, nullptr, kkh,     1, 1 };  // kk fp16 row only
    pa.t[2] = { vh, Wvh, bv, nullptr, vvT,     2, 1 };  // vv fp16 transposed only
    pa.t[3] = { qh, Wkh, bk, qk,      nullptr, 0, 0 };  // q_k fp32
    pa.t[4] = { qh, Wvh, bv, qv,      nullptr, 0, 0 };  // q_v fp32
    h_proj<<<dim3(FD / 128, SQ / 128, 5), 256, gSmem>>>(pa);

    // 3) q_att diag term + den init with sink term (must precede scores)
    qatt_kernel<<<SQ / 8, 256>>>(qq, qk, qatt, den);

    // 4) scores GEMM with fused exp + den accumulation (softmax kernel gone)
    h_gemm_nt<0><<<dim3(SQ / 128, SQ / 128), 256, gSmem>>>(
        qqh, kkh, ebf, FD, SQ, nullptr, nullptr, den);

    // 5) res = (E @ vv)/den + qv*qatt  -> fp16 resh
    h_gemm_nt<1><<<dim3(FD / 128, SQ / 128), 256, gSmem>>>(
        ebf, vvT, resh, SQ, FD, qv, qatt, den);

    // 6) y = relu(res @ Wo^T + bo)  (fp16 HMMA, fp32 out)
    ProjArgs po;
    po.t[0] = { resh, Woh, bo, out, nullptr, 0, 1 };
    po.t[1] = po.t[0]; po.t[2] = po.t[0]; po.t[3] = po.t[0]; po.t[4] = po.t[0];
    h_proj<<<dim3(FD / 128, SQ / 128, 1), 256, gSmem>>>(po);
}

// round 14
// speedup vs baseline: 1.0689x; 1.0281x over previous
#include <cuda_runtime.h>
#include <cuda_fp16.h>
#include <math.h>
#include <cstdint>

#define SQ 4096
#define FD 512

// ---- scratch (allocation-free: __device__ globals) ----
__device__ float g_qq[SQ * FD];      // fp32 qq (for qatt)
__device__ float g_qk[SQ * FD];      // fp32 q@Wk^T+bk (for qatt)
__device__ float g_qv[SQ * FD];      // fp32 q@Wv^T+bv (res epilogue)
__device__ float g_qatt[SQ];
__device__ float g_den[SQ];
__device__ __half g_qh[SQ * FD];     // fp16 inputs
__device__ __half g_kh[SQ * FD];
__device__ __half g_vh[SQ * FD];
__device__ __half g_Wqh[FD * FD];    // fp16 weights
__device__ __half g_Wkh[FD * FD];
__device__ __half g_Wvh[FD * FD];
__device__ __half g_Woh[FD * FD];
__device__ __half g_qqh[SQ * FD];    // fp16 relu'd projections
__device__ __half g_kkh[SQ * FD];
__device__ __half g_vvT[FD * SQ];    // vv transposed, K-major
__device__ __half g_resh[SQ * FD];   // fp16 res (A of out-proj)
__device__ __half g_ebf[(size_t)SQ * SQ];  // fp16 un-normalized exp (32MB)

#define INV_SCALE 0.04419417382415922f   // 1/sqrt(513)
#define EXP_SHIFT 4.1588830833596715f    // 6*ln2 : keeps fp16 exp in range

// ================= helpers =================
__device__ __forceinline__ uint32_t smem_u32(const void* p) {
    uint32_t a;
    asm("{ .reg .u64 t; cvta.to.shared.u64 t, %1; cvt.u32.u64 %0, t; }" : "=r"(a) : "l"(p));
    return a;
}
__device__ __forceinline__ void ldsm4(uint32_t* r, uint32_t a) {
    asm volatile("ldmatrix.sync.aligned.m8n8.x4.shared.b16 {%0,%1,%2,%3}, [%4];"
                 : "=r"(r[0]), "=r"(r[1]), "=r"(r[2]), "=r"(r[3]) : "r"(a));
}
// NOTE: non-volatile — pure register op, lets ptxas schedule HMMA under LDSM latency
__device__ __forceinline__ void mma16816(float* c, const uint32_t* a, uint32_t b0, uint32_t b1) {
    asm("mma.sync.aligned.m16n8k16.row.col.f32.f16.f16.f32 "
        "{%0,%1,%2,%3}, {%4,%5,%6,%7}, {%8,%9}, {%0,%1,%2,%3};"
        : "+f"(c[0]), "+f"(c[1]), "+f"(c[2]), "+f"(c[3])
        : "r"(a[0]), "r"(a[1]), "r"(a[2]), "r"(a[3]), "r"(b0), "r"(b1));
}
__device__ __forceinline__ void cp16(uint32_t s, const void* g) {
    asm volatile("cp.async.cg.shared.global [%0], [%1], 16;" :: "r"(s), "l"(g));
}
#define CP_COMMIT() asm volatile("cp.async.commit_group;" ::: "memory")
#define CP_WAIT0()  asm volatile("cp.async.wait_group 0;" ::: "memory")
#define CP_WAIT1()  asm volatile("cp.async.wait_group 1;" ::: "memory")

// smem geometry: row = 32 halfs + 8 pad = 80B. BM=128; BN = 32*G.
#define SAS 40
#define STAGE_A_BYTES (128 * 80)

// ---- fragment set for one 16-K slice of the warp tile ----
template <int G>
struct Frags { uint32_t a[2][4]; uint32_t b[G][4]; };

template <int G>
__device__ __forceinline__ void load_frags(Frags<G>& f, uint32_t smA, uint32_t smB,
                                           int ks, int wm, int wn, int lane) {
    const int rowA = lane & 15, koffA = (lane >> 4) * 8;
    const int noffB = (lane & 7) + ((lane >> 4) << 3), koffB = ((lane >> 3) & 1) * 8;
#pragma unroll
    for (int fm = 0; fm < 2; fm++)
        ldsm4(f.a[fm], smA + (uint32_t)(((wm * 32 + fm * 16 + rowA) * SAS + ks * 16 + koffA) * 2));
#pragma unroll
    for (int g = 0; g < G; g++)
        ldsm4(f.b[g], smB + (uint32_t)(((wn * 16 * G + g * 16 + noffB) * SAS + ks * 16 + koffB) * 2));
}

template <int G>
__device__ __forceinline__ void mma_frags(float (&c)[2][2 * G][4], const Frags<G>& f) {
#pragma unroll
    for (int fm = 0; fm < 2; fm++)
#pragma unroll
        for (int g = 0; g < G; g++) {
            mma16816(c[fm][2 * g], f.a[fm], f.b[g][0], f.b[g][1]);
            mma16816(c[fm][2 * g + 1], f.a[fm], f.b[g][2], f.b[g][3]);
        }
}

// ============================================================
// fp16 NT GEMM: C = A[M,K] @ B[N,K]^T, fp32 accum, 3-stage cp.async.
// BM=128, BN=32G, 256 thr (8 warps 4m x 2n), warp tile 32 x 16G.
// EPI 0: exp fusion -> fp16 exp + atomicAdd den.  EPI 1: res epilogue.
// ============================================================
template <int G, int EPI>
__global__ void __launch_bounds__(256)
h_gemm_nt(const __half* __restrict__ A, const __half* __restrict__ B,
          __half* __restrict__ O, int K, int ldc,
          const float* __restrict__ qv, const float* __restrict__ qatt,
          float* __restrict__ den) {
    constexpr int BN = 32 * G;
    constexpr int STAGE_B = BN * 80;
    extern __shared__ char dsm[];
    const uint32_t baseA = smem_u32(dsm);
    const uint32_t baseB = baseA + 3 * STAGE_A_BYTES;

    const int tid = threadIdx.x, lane = tid & 31, wid = tid >> 5;
    const int wm = wid & 3, wn = wid >> 2;
    const int m0 = blockIdx.y * 128, n0 = blockIdx.x * BN;

    const int cr = tid >> 2;
    const int cc = (tid & 3) * 8;
    const int n = K >> 5;

    auto issue = [&](int chunk) {
        const int s = chunk % 3;
        const int k0 = chunk << 5;
        const uint32_t sa = baseA + s * STAGE_A_BYTES;
        const uint32_t sb = baseB + s * STAGE_B;
        cp16(sa + cr * 80 + cc * 2, A + (size_t)(m0 + cr) * K + k0 + cc);
        cp16(sa + (cr + 64) * 80 + cc * 2, A + (size_t)(m0 + cr + 64) * K + k0 + cc);
#pragma unroll
        for (int r = 0; r < BN; r += 64)
            cp16(sb + (cr + r) * 80 + cc * 2, B + (size_t)(n0 + cr + r) * K + k0 + cc);
        CP_COMMIT();
    };

    issue(0);
    issue(1);

    float c[2][2 * G][4] = {};

    for (int it = 0; it < n; it++) {
        if (it + 1 < n) { CP_WAIT1(); } else { CP_WAIT0(); }
        __syncthreads();
        if (it + 2 < n) issue(it + 2);
        const uint32_t smA = baseA + (it % 3) * STAGE_A_BYTES;
        const uint32_t smB = baseB + (it % 3) * STAGE_B;
        Frags<G> f0, f1;
        load_frags<G>(f0, smA, smB, 0, wm, wn, lane);
        load_frags<G>(f1, smA, smB, 1, wm, wn, lane);
        mma_frags<G>(c, f0);
        mma_frags<G>(c, f1);
    }

    // ---- epilogue ----
    const int rbase = m0 + wm * 32 + (lane >> 2);
    const int cbase = n0 + wn * 16 * G + (lane & 3) * 2;
#pragma unroll
    for (int fm = 0; fm < 2; fm++) {
        const int r = rbase + fm * 16;
        if (EPI == 0) {
            float p0 = 0.0f, p1 = 0.0f;
#pragma unroll
            for (int j = 0; j < 2 * G; j++) {
                const int col = cbase + j * 8;
                float e0 = __expf(c[fm][j][0] * INV_SCALE - EXP_SHIFT);
                float e1 = __expf(c[fm][j][1] * INV_SCALE - EXP_SHIFT);
                float e2 = __expf(c[fm][j][2] * INV_SCALE - EXP_SHIFT);
                float e3 = __expf(c[fm][j][3] * INV_SCALE - EXP_SHIFT);
                *(__half2*)(O + (size_t)r * ldc + col) = __floats2half2_rn(e0, e1);
                *(__half2*)(O + (size_t)(r + 8) * ldc + col) = __floats2half2_rn(e2, e3);
                p0 += e0 + e1;
                p1 += e2 + e3;
            }
            p0 += __shfl_xor_sync(0xffffffffu, p0, 1);
            p0 += __shfl_xor_sync(0xffffffffu, p0, 2);
            p1 += __shfl_xor_sync(0xffffffffu, p1, 1);
            p1 += __shfl_xor_sync(0xffffffffu, p1, 2);
            if ((lane & 3) == 0) {
                atomicAdd(den + r, p0);
                atomicAdd(den + r + 8, p1);
            }
        } else {
            const float i0 = __frcp_rn(den[r]),     qa0 = qatt[r];
            const float i1 = __frcp_rn(den[r + 8]), qa1 = qatt[r + 8];
#pragma unroll
            for (int j = 0; j < 2 * G; j++) {
                const int col = cbase + j * 8;
                float2 v0 = *(const float2*)(qv + (size_t)r * ldc + col);
                float2 v1 = *(const float2*)(qv + (size_t)(r + 8) * ldc + col);
                *(__half2*)(O + (size_t)r * ldc + col) =
                    __floats2half2_rn(c[fm][j][0] * i0 + v0.x * qa0, c[fm][j][1] * i0 + v0.y * qa0);
                *(__half2*)(O + (size_t)(r + 8) * ldc + col) =
                    __floats2half2_rn(c[fm][j][2] * i1 + v1.x * qa1, c[fm][j][3] * i1 + v1.y * qa1);
            }
        }
    }
}

// ============================================================
// fp16 NT GEMM (projections), z-fused table, G=4 (BN=128).
// ============================================================
struct ProjTab {
    const __half* A; const __half* B; const float* bias;
    float* Cf; __half* Ch; int hm; int relu;
};
struct ProjArgs { ProjTab t[5]; };

__global__ void __launch_bounds__(256)
h_proj(ProjArgs pa) {
    constexpr int G = 4, BN = 128;
    constexpr int STAGE_B = BN * 80;
    const ProjTab T = pa.t[blockIdx.z];
    const __half* __restrict__ A = T.A;
    const __half* __restrict__ B = T.B;
    const int K = FD, N = FD;
    extern __shared__ char dsm[];
    const uint32_t baseA = smem_u32(dsm);
    const uint32_t baseB = baseA + 3 * STAGE_A_BYTES;

    const int tid = threadIdx.x, lane = tid & 31, wid = tid >> 5;
    const int wm = wid & 3, wn = wid >> 2;
    const int m0 = blockIdx.y * 128, n0 = blockIdx.x * BN;

    const int cr = tid >> 2;
    const int cc = (tid & 3) * 8;
    const int n = K >> 5;  // 16

    auto issue = [&](int chunk) {
        const int s = chunk % 3;
        const int k0 = chunk << 5;
        const uint32_t sa = baseA + s * STAGE_A_BYTES;
        const uint32_t sb = baseB + s * STAGE_B;
        cp16(sa + cr * 80 + cc * 2, A + (size_t)(m0 + cr) * K + k0 + cc);
        cp16(sa + (cr + 64) * 80 + cc * 2, A + (size_t)(m0 + cr + 64) * K + k0 + cc);
        cp16(sb + cr * 80 + cc * 2, B + (size_t)(n0 + cr) * K + k0 + cc);
        cp16(sb + (cr + 64) * 80 + cc * 2, B + (size_t)(n0 + cr + 64) * K + k0 + cc);
        CP_COMMIT();
    };

    issue(0);
    issue(1);

    float c[2][2 * G][4] = {};

    for (int it = 0; it < n; it++) {
        if (it + 1 < n) { CP_WAIT1(); } else { CP_WAIT0(); }
        __syncthreads();
        if (it + 2 < n) issue(it + 2);
        const uint32_t smA = baseA + (it % 3) * STAGE_A_BYTES;
        const uint32_t smB = baseB + (it % 3) * STAGE_B;
        Frags<G> f0, f1;
        load_frags<G>(f0, smA, smB, 0, wm, wn, lane);
        load_frags<G>(f1, smA, smB, 1, wm, wn, lane);
        mma_frags<G>(c, f0);
        mma_frags<G>(c, f1);
    }

    // ---- epilogue ----
    const int rbase = m0 + wm * 32 + (lane >> 2);
    const int cbase = n0 + wn * 16 * G + (lane & 3) * 2;
    float* Cf = T.Cf;
    __half* Ch = T.Ch;
    const int hm = T.hm, relu = T.relu;
#pragma unroll
    for (int fm = 0; fm < 2; fm++) {
#pragma unroll
        for (int j = 0; j < 2 * G; j++) {
            const int col = cbase + j * 8;
            const float b0 = T.bias[col], b1 = T.bias[col + 1];
#pragma unroll
            for (int h = 0; h < 2; h++) {
                const int r = rbase + fm * 16 + h * 8;
                float v0 = c[fm][j][2 * h] + b0;
                float v1 = c[fm][j][2 * h + 1] + b1;
                if (relu) { v0 = fmaxf(v0, 0.0f); v1 = fmaxf(v1, 0.0f); }
                if (Cf) *(float2*)(Cf + (size_t)r * N + col) = make_float2(v0, v1);
                if (hm == 1) {
                    *(__half2*)(Ch + (size_t)r * N + col) = __floats2half2_rn(v0, v1);
                } else if (hm == 2) {
                    Ch[(size_t)col * SQ + r] = __float2half_rn(v0);
                    Ch[(size_t)(col + 1) * SQ + r] = __float2half_rn(v1);
                }
            }
        }
    }
}

// ============================================================
// fp32 -> fp16 conversion, z-segmented
// ============================================================
struct CvtTab { const float* src; __half* dst; int n; };
struct CvtArgs { CvtTab t[7]; };

__global__ void f2h_kernel(CvtArgs a) {
    const CvtTab T = a.t[blockIdx.z];
    const int i = (blockIdx.x * blockDim.x + threadIdx.x) * 4;
    if (i < T.n) {
        float4 v = *(const float4*)(T.src + i);
        __half2 h0 = __floats2half2_rn(v.x, v.y);
        __half2 h1 = __floats2half2_rn(v.z, v.w);
        *(uint2*)(T.dst + i) = make_uint2(*(uint32_t*)&h0, *(uint32_t*)&h1);
    }
}

// ============================================================
// q_att[s] = sum_f qq[s,f]*qk[s,f]; den[s] = exp sink term
// ============================================================
__global__ void qatt_kernel(const float* __restrict__ qq, const float* __restrict__ qk,
                            float* __restrict__ qatt, float* __restrict__ den) {
    const int warp = (blockIdx.x * blockDim.x + threadIdx.x) >> 5;
    const int lane = threadIdx.x & 31;
    if (warp >= SQ) return;
    const float4* a = (const float4*)(qq + (size_t)warp * FD);
    const float4* b = (const float4*)(qk + (size_t)warp * FD);
    float sum = 0.0f;
#pragma unroll
    for (int i = lane; i < FD / 4; i += 32) {
        float4 x = a[i], y = b[i];
        sum = fmaf(x.x, y.x, sum); sum = fmaf(x.y, y.y, sum);
        sum = fmaf(x.z, y.z, sum); sum = fmaf(x.w, y.w, sum);
    }
#pragma unroll
    for (int o = 16; o; o >>= 1) sum += __shfl_xor_sync(0xffffffffu, sum, o);
    if (lane == 0) {
        qatt[warp] = sum;
        den[warp] = __expf(sum * INV_SCALE - EXP_SHIFT);
    }
}

// ============================================================
extern "C" void kernel_launch(void* const* d_in, const int* in_sizes, int n_in,
                              void* d_out, int out_size) {
    const float* q  = (const float*)d_in[0];
    const float* k  = (const float*)d_in[1];
    const float* v  = (const float*)d_in[2];
    const float* Wq = (const float*)d_in[3];
    const float* bq = (const float*)d_in[4];
    const float* Wk = (const float*)d_in[5];
    const float* bk = (const float*)d_in[6];
    const float* Wv = (const float*)d_in[7];
    const float* bv = (const float*)d_in[8];
    const float* Wo = (const float*)d_in[9];
    const float* bo = (const float*)d_in[10];
    float* out = (float*)d_out;

    float *qq, *qk, *qv, *qatt, *den;
    __half *qh, *kh, *vh, *Wqh, *Wkh, *Wvh, *Woh;
    __half *qqh, *kkh, *vvT, *resh, *ebf;
    cudaGetSymbolAddress((void**)&qq, g_qq);
    cudaGetSymbolAddress((void**)&qk, g_qk);
    cudaGetSymbolAddress((void**)&qv, g_qv);
    cudaGetSymbolAddress((void**)&qatt, g_qatt);
    cudaGetSymbolAddress((void**)&den, g_den);
    cudaGetSymbolAddress((void**)&qh, g_qh);
    cudaGetSymbolAddress((void**)&kh, g_kh);
    cudaGetSymbolAddress((void**)&vh, g_vh);
    cudaGetSymbolAddress((void**)&Wqh, g_Wqh);
    cudaGetSymbolAddress((void**)&Wkh, g_Wkh);
    cudaGetSymbolAddress((void**)&Wvh, g_Wvh);
    cudaGetSymbolAddress((void**)&Woh, g_Woh);
    cudaGetSymbolAddress((void**)&qqh, g_qqh);
    cudaGetSymbolAddress((void**)&kkh, g_kkh);
    cudaGetSymbolAddress((void**)&vvT, g_vvT);
    cudaGetSymbolAddress((void**)&resh, g_resh);
    cudaGetSymbolAddress((void**)&ebf, g_ebf);

    const int smem4 = 3 * STAGE_A_BYTES + 3 * 128 * 80;  // 61440 (G=4)
    const int smem2 = 3 * STAGE_A_BYTES + 3 * 64 * 80;   // 46080 (G=2)
    cudaFuncSetAttribute((const void*)h_gemm_nt<4, 0>, cudaFuncAttributeMaxDynamicSharedMemorySize, smem4);
    cudaFuncSetAttribute((const void*)h_gemm_nt<2, 1>, cudaFuncAttributeMaxDynamicSharedMemorySize, smem2);
    cudaFuncSetAttribute((const void*)h_proj, cudaFuncAttributeMaxDynamicSharedMemorySize, smem4);

    // 1) fp32 -> fp16 conversions (inputs + weights)
    CvtArgs ca;
    ca.t[0] = { q, qh, SQ * FD };
    ca.t[1] = { k, kh, SQ * FD };
    ca.t[2] = { v, vh, SQ * FD };
    ca.t[3] = { Wq, Wqh, FD * FD };
    ca.t[4] = { Wk, Wkh, FD * FD };
    ca.t[5] = { Wv, Wvh, FD * FD };
    ca.t[6] = { Wo, Woh, FD * FD };
    f2h_kernel<<<dim3(SQ * FD / 1024, 1, 7), 256>>>(ca);

    // 2) 5 fused projections (fp16 HMMA, BN=128)
    ProjArgs pa;
    pa.t[0] = { qh, Wqh, bq, qq,      qqh,     1, 1 };
    pa.t[1] = { kh, Wkh, bk, nullptr, kkh,     1, 1 };
    pa.t[2] = { vh, Wvh, bv, nullptr, vvT,     2, 1 };
    pa.t[3] = { qh, Wkh, bk, qk,      nullptr, 0, 0 };
    pa.t[4] = { qh, Wvh, bv, qv,      nullptr, 0, 0 };
    h_proj<<<dim3(FD / 128, SQ / 128, 5), 256, smem4>>>(pa);

    // 3) q_att diag term + den init with sink term
    qatt_kernel<<<SQ / 8, 256>>>(qq, qk, qatt, den);

    // 4) scores GEMM with fused exp + den accumulation (G=4, 1024 CTAs)
    h_gemm_nt<4, 0><<<dim3(SQ / 128, SQ / 128), 256, smem4>>>(
        qqh, kkh, ebf, FD, SQ, nullptr, nullptr, den);

    // 5) res = (E @ vv)/den + qv*qatt  (G=2 -> 256 CTAs, better SM fill)
    h_gemm_nt<2, 1><<<dim3(FD / 64, SQ / 128), 256, smem2>>>(
        ebf, vvT, resh, SQ, FD, qv, qatt, den);

    // 6) y = relu(res @ Wo^T + bo)
    ProjArgs po;
    po.t[0] = { resh, Woh, bo, out, nullptr, 0, 1 };
    po.t[1] = po.t[0]; po.t[2] = po.t[0]; po.t[3] = po.t[0]; po.t[4] = po.t[0];
    h_proj<<<dim3(FD / 128, SQ / 128, 1), 256, smem4>>>(po);
}